// round 13
// baseline (speedup 1.0000x reference)
#include <cuda_runtime.h>
#include <cstdint>

typedef unsigned long long ull;

#define SEQ   256
#define BSZ   2048
#define FDIM  5
#define HDIM  64
#define KAUX  8
#define NCOL  1280           // 256 (main gates) + 8*128 (aux gates)
#define BT    16             // batch rows per block
#define NTHR  640            // 20 warps: 2 row-groups x 320 col-quads
#define NBLK  (BSZ / BT)     // 128 blocks, 1 per SM
#define NX    720            // 9*16*5 staged x values per step
#define HTS   20             // hhT row stride in floats (80B, 16B-aligned)

#define CHPS  12             // chunks per step: 8 Ucat + 4 W2
#define TOTC  (CHPS * SEQ)   // total chunks over the sequence

// ---------------- repacked weights (device globals; prep kernel fills) ------
__device__ __align__(16) float g_Ucat[HDIM * NCOL];   // [h][col]  recurrent cat
__device__ __align__(16) float g_Wx[FDIM * NCOL];     // [f][col]  input proj cat
__device__ __align__(16) float g_bcat[NCOL];          // bias cat
__device__ __align__(16) float g_W2[128 * 256];       // [h<64:Wih^T, h>=64:Whh^T][j]
__device__ __align__(16) float g_b2[256];             // b_ih + b_hh
__device__ __align__(16) float g_WattT[HDIM * HDIM];  // [g][h] = W_att[h][g]
__device__ __align__(16) float g_linW[HDIM];

// ---------------- f32x2 helpers ---------------------------------------------
__device__ __forceinline__ void fma2(ull &d, ull a, ull b) {
    asm("fma.rn.f32x2 %0, %1, %2, %0;" : "+l"(d) : "l"(a), "l"(b));
}
__device__ __forceinline__ ull pkdup(float v) {
    ull r; asm("mov.b64 %0, {%1,%1};" : "=l"(r) : "f"(v)); return r;
}
__device__ __forceinline__ void upk(ull v, float &lo, float &hi) {
    asm("mov.b64 {%0,%1}, %2;" : "=f"(lo), "=f"(hi) : "l"(v));
}

// ---------------- fast activations ------------------------------------------
__device__ __forceinline__ float fsig(float x) {
    float e = __expf(-x);
    return __fdividef(1.f, 1.f + e);
}
__device__ __forceinline__ float ftanh(float x) {
    return 2.f * fsig(2.f * x) - 1.f;
}
// branch-free sig/tanh: out = fsig(x*am)*asc + ab  (sig: 1,1,0 ; tanh: 2,2,-1)
__device__ __forceinline__ float actp(float x, float am, float asc, float ab) {
    return fmaf(fsig(x * am), asc, ab);
}

// ---------------- mbarrier / bulk-copy PTX ----------------------------------
#define MB_INIT(addr, cnt) \
    asm volatile("mbarrier.init.shared.b64 [%0], %1;" :: "r"(addr), "r"(cnt) : "memory")
#define MB_EXPECT_TX(addr, bytes) \
    asm volatile("mbarrier.arrive.expect_tx.shared.b64 _, [%0], %1;" :: "r"(addr), "r"(bytes) : "memory")
#define MB_ARRIVE(addr) \
    asm volatile("mbarrier.arrive.shared.b64 _, [%0];" :: "r"(addr) : "memory")
#define MB_WAIT(addr, par) do {                                                 \
    uint32_t _m = (addr), _p = (par), _d;                                       \
    asm volatile("{\n\t.reg .pred p;\n\t"                                       \
        "mbarrier.try_wait.parity.acquire.cta.shared::cta.b64 p, [%1], %2;\n\t" \
        "selp.b32 %0, 1, 0, p;\n\t}"                                            \
        : "=r"(_d) : "r"(_m), "r"(_p) : "memory");                              \
    if (!_d) {                                                                  \
        asm volatile("{\n\t.reg .pred P1;\n\t"                                  \
            "W_%=:\n\t"                                                         \
            "mbarrier.try_wait.parity.acquire.cta.shared::cta.b64 P1, [%0], %1, 0x989680;\n\t" \
            "@P1 bra.uni D_%=;\n\t"                                             \
            "bra.uni W_%=;\n\t"                                                 \
            "D_%=:\n\t}" :: "r"(_m), "r"(_p) : "memory");                       \
    }                                                                           \
} while (0)
#define BULK_G2S(dst, src, bytes, mbar) \
    asm volatile("cp.async.bulk.shared::cluster.global.mbarrier::complete_tx::bytes " \
                 "[%0], [%1], %2, [%3];" \
                 :: "r"(dst), "l"((const void *)(src)), "r"(bytes), "r"(mbar) : "memory")

// producer: issue DMA for chunk cj (tid 0 only)
__device__ __forceinline__ void produce(int cj, uint32_t ringb, uint32_t mbf0, uint32_t mbe0) {
    if (cj >= TOTC) return;
    if (cj >= 2) MB_WAIT(mbe0 + (cj & 1) * 8, ((cj >> 1) + 1) & 1);
    int m = cj % CHPS;
    const float *src;
    uint32_t bytes;
    if (m < 8) { src = g_Ucat + m * (8 * NCOL);       bytes = 8 * NCOL * 4; }   // 40960
    else       { src = g_W2   + (m - 8) * (32 * 256); bytes = 32 * 256 * 4; }   // 32768
    uint32_t fb = mbf0 + (cj & 1) * 8;
    MB_EXPECT_TX(fb, bytes);
    BULK_G2S(ringb + (cj & 1) * 40960u, src, bytes, fb);
}

// ---------------- prep: repack weights --------------------------------------
__global__ void prep_kernel(const float *__restrict__ Wm, const float *__restrict__ Um,
                            const float *__restrict__ bm, const float *__restrict__ Wa,
                            const float *__restrict__ Ua, const float *__restrict__ ba,
                            const float *__restrict__ Watt, const float *__restrict__ Wih,
                            const float *__restrict__ Whh, const float *__restrict__ bih,
                            const float *__restrict__ bhh, const float *__restrict__ linW) {
    int i = blockIdx.x * blockDim.x + threadIdx.x;
    if (i < HDIM * NCOL) {
        int h = i / NCOL, col = i % NCOL;
        float v;
        if (col < 256) v = Um[h * 256 + col];
        else { int cc = col - 256; int k = cc >> 7, j = cc & 127; v = Ua[(k * HDIM + h) * 128 + j]; }
        g_Ucat[i] = v;
    }
    if (i < FDIM * NCOL) {
        int f = i / NCOL, col = i % NCOL;
        float v;
        if (col < 256) v = Wm[f * 256 + col];
        else { int cc = col - 256; int k = cc >> 7, j = cc & 127; v = Wa[(k * FDIM + f) * 128 + j]; }
        g_Wx[i] = v;
    }
    if (i < NCOL) g_bcat[i] = (i < 256) ? bm[i] : ba[i - 256];
    if (i < 128 * 256) {
        int h = i / 256, j = i % 256;
        g_W2[i] = (h < 64) ? Wih[j * 64 + h] : Whh[j * 64 + (h - 64)];
    }
    if (i < 256) g_b2[i] = bih[i] + bhh[i];
    if (i < HDIM * HDIM) { int g = i / HDIM, h = i % HDIM; g_WattT[i] = Watt[h * HDIM + g]; }
    if (i < HDIM) g_linW[i] = linW[i];
}

// ---------------- smem layout (float offsets) -------------------------------
#define SM_G    0                       // G[16][1280] activated    20480
#define SM_G2   20480                   // g2[16][256] activated     4096
#define SM_HT   24576                   // hhT[128][20]              2560
#define SM_C    27136                   // c1[16][64]                1024
#define SM_X    28160                   // x double buffer 2x720     1440
#define SM_RING 29600                   // 2 x 10240 weight ring    20480
#define SM_MB   50080                   // 4 mbarriers (8 floats)       8
#define SM_PT   50088                   // 9 input base ptrs (18 fl)   20
#define SM_V    50108                   // vsm[16][64] attn matvec   1024
#define SM_TOT  51132                   // 204528 bytes

__global__ void __launch_bounds__(NTHR, 1)
mi_kernel(const float *__restrict__ Y,
          const float *__restrict__ X1, const float *__restrict__ X2,
          const float *__restrict__ X3, const float *__restrict__ X4,
          const float *__restrict__ X5, const float *__restrict__ X6,
          const float *__restrict__ X7, const float *__restrict__ X8,
          const float *__restrict__ batt_p, const float *__restrict__ linb_p,
          float *__restrict__ out) {
    extern __shared__ float sm[];
    float *Gsm  = sm + SM_G;
    float *g2   = sm + SM_G2;
    float *hhT  = sm + SM_HT;     // [h(0..63:h1, 64..127:h2)][row], stride HTS
    float *csm  = sm + SM_C;
    float *xsm  = sm + SM_X;      // two 720-float buffers
    float *ring = sm + SM_RING;
    float *vsm  = sm + SM_V;      // v[r][h] = (W_att @ c(t-1))[h]
    const float **ptab = (const float **)(sm + SM_PT);

    uint32_t sbase;
    asm("{ .reg .u64 t; cvta.to.shared.u64 t, %1; cvt.u32.u64 %0, t; }"
        : "=r"(sbase) : "l"(sm));
    const uint32_t ringb = sbase + SM_RING * 4;
    const uint32_t mbf0  = sbase + SM_MB * 4;        // full[0], full[1]
    const uint32_t mbe0  = mbf0 + 16;                // empty[0], empty[1]

    const int tid  = threadIdx.x;
    const int warp = tid >> 5, lane = tid & 31;
    const int rg = (tid >= 320) ? 1 : 0;   // row-group: rows 8rg..8rg+7
    const int q  = tid - rg * 320;         // col-quad 0..319 (cols 4q..4q+3)
    const int c0 = 4 * q;
    const int b0 = blockIdx.x * BT;

    const float batt = *batt_p;
    const float linb = *linb_p;

    // phase-1 quad metadata
    const bool p1_sig = (c0 < 256) ? ((c0 >> 6) < 3) : (((c0 - 256) & 127) < 64);
    const int  xsrc   = (c0 < 256) ? 0 : 1 + ((c0 - 256) >> 7);
    const float am1 = p1_sig ? 1.f : 2.f, as1 = p1_sig ? 1.f : 2.f, ab1 = p1_sig ? 0.f : -1.f;

    // phase-2 mapping (threads 0..127): 2 row-groups x 64 col-quads, 8 rows ea
    const int rg2 = tid >> 6;              // 0/1 -> rows 8*rg2..8*rg2+7
    const int q2  = tid & 63;              // cols 4*q2..4*q2+3
    const int c2c = 4 * q2;
    const bool p2_sig = ((c2c >> 6) != 2);
    const float am2 = p2_sig ? 1.f : 2.f, as2 = p2_sig ? 1.f : 2.f, ab2 = p2_sig ? 0.f : -1.f;

    // attention matvec mapping (threads 128..383): 16 rows x 16 col-quads
    const int mv  = tid - 128;             // 0..255
    const int vr  = mv >> 4;               // row 0..15
    const int vc  = 4 * (mv & 15);         // col 0,4,..,60

    // init: ptr table, mbarriers, zero state
    {
        const float *xin[9] = {Y, X1, X2, X3, X4, X5, X6, X7, X8};
        if (tid < 9) ptab[tid] = xin[tid];
    }
    if (tid == 0) {
        MB_INIT(mbf0, 1);  MB_INIT(mbf0 + 8, 1);
        MB_INIT(mbe0, 20); MB_INIT(mbe0 + 8, 20);   // one arrive per warp
    }
    for (int i = tid; i < 128 * HTS; i += NTHR) hhT[i] = 0.f;
    for (int i = tid; i < 1024; i += NTHR) csm[i] = 0.f;
    float c1a = 0.f, c1b = 0.f;   // phase-1 cell, h = lane / lane+32 of row `warp`
    float c2a = 0.f, c2b = 0.f;   // phase-2 cell
    __syncthreads();

    // stage inputs for t=0 into buffer 0; set up per-thread prefetch pointers
    for (int j = tid; j < NX; j += NTHR) {
        int s = j / 80, rem = j - s * 80;
        int row = rem / 5, f = rem - row * 5;
        xsm[s * 80 + f * 16 + row] = ptab[s][(size_t)b0 * FDIM + rem];
    }
    const int j0 = tid, j1 = tid + NTHR;           // j1 < 720 only for tid<80
    const int s0 = j0 / 80, rem0 = j0 - s0 * 80;
    const int d0 = s0 * 80 + (rem0 % 5) * 16 + rem0 / 5;
    const int s1 = (j1 < NX) ? j1 / 80 : 0;
    const int rem1 = j1 - s1 * 80;
    const int d1 = (j1 < NX) ? s1 * 80 + (rem1 % 5) * 16 + rem1 / 5 : 0;
    const float *pp0 = ptab[s0] + (size_t)b0 * FDIM + rem0;
    const float *pp1 = ptab[s1] + (size_t)b0 * FDIM + rem1;

    __syncthreads();
    if (tid == 0) produce(0, ringb, mbf0, mbe0);    // kick off the ring
    int ci = 0;                                     // global chunk cursor

    for (int t = 0; t < SEQ; t++) {
        const float *xcur = xsm + (t & 1) * NX;
        float *xnxt = xsm + ((t + 1) & 1) * NX;

        // ---- issue x(t+1) loads now; stored at end of step (latency hidden)
        float pv0, pv1 = 0.f;
        {
            size_t toff = (size_t)((t + 1 < SEQ) ? t + 1 : t) * (BSZ * FDIM);
            pv0 = __ldg(pp0 + toff);
            if (j1 < NX) pv1 = __ldg(pp1 + toff);
        }

        // ================= PHASE A: both GEMMs + attn matvec =================
        // phase-1 GEMM(t): G = act(b + x(t)@Wx + h1(t-1)@Ucat)
        {
            ull acc[8][2];
            {
                ulonglong2 bq = *(const ulonglong2 *)&g_bcat[c0];
#pragma unroll
                for (int r = 0; r < 8; r++) { acc[r][0] = bq.x; acc[r][1] = bq.y; }
            }
            // x contribution (K=5)
#pragma unroll
            for (int f = 0; f < FDIM; f++) {
                ulonglong2 w = *(const ulonglong2 *)&g_Wx[f * NCOL + c0];
                const float *xb = &xcur[xsrc * 80 + f * 16 + 8 * rg];
                float4 xa = *(const float4 *)xb;
                float4 xc = *(const float4 *)(xb + 4);
                fma2(acc[0][0], pkdup(xa.x), w.x); fma2(acc[0][1], pkdup(xa.x), w.y);
                fma2(acc[1][0], pkdup(xa.y), w.x); fma2(acc[1][1], pkdup(xa.y), w.y);
                fma2(acc[2][0], pkdup(xa.z), w.x); fma2(acc[2][1], pkdup(xa.z), w.y);
                fma2(acc[3][0], pkdup(xa.w), w.x); fma2(acc[3][1], pkdup(xa.w), w.y);
                fma2(acc[4][0], pkdup(xc.x), w.x); fma2(acc[4][1], pkdup(xc.x), w.y);
                fma2(acc[5][0], pkdup(xc.y), w.x); fma2(acc[5][1], pkdup(xc.y), w.y);
                fma2(acc[6][0], pkdup(xc.z), w.x); fma2(acc[6][1], pkdup(xc.z), w.y);
                fma2(acc[7][0], pkdup(xc.w), w.x); fma2(acc[7][1], pkdup(xc.w), w.y);
            }
            // h contribution: 8 ring chunks x 8 h-rows
            for (int hc = 0; hc < 8; hc++) {
                if (tid == 0) produce(ci + 1, ringb, mbf0, mbe0);
                MB_WAIT(mbf0 + (ci & 1) * 8, (ci >> 1) & 1);
                const float *wb = ring + (ci & 1) * 10240;
#pragma unroll
                for (int h2 = 0; h2 < 8; h2++) {
                    int h = hc * 8 + h2;
                    ulonglong2 w = *(const ulonglong2 *)&wb[h2 * NCOL + c0];
                    const float *hp = &hhT[h * HTS + 8 * rg];
                    float4 ha = *(const float4 *)hp;
                    float4 hb2 = *(const float4 *)(hp + 4);
                    fma2(acc[0][0], pkdup(ha.x), w.x);  fma2(acc[0][1], pkdup(ha.x), w.y);
                    fma2(acc[1][0], pkdup(ha.y), w.x);  fma2(acc[1][1], pkdup(ha.y), w.y);
                    fma2(acc[2][0], pkdup(ha.z), w.x);  fma2(acc[2][1], pkdup(ha.z), w.y);
                    fma2(acc[3][0], pkdup(ha.w), w.x);  fma2(acc[3][1], pkdup(ha.w), w.y);
                    fma2(acc[4][0], pkdup(hb2.x), w.x); fma2(acc[4][1], pkdup(hb2.x), w.y);
                    fma2(acc[5][0], pkdup(hb2.y), w.x); fma2(acc[5][1], pkdup(hb2.y), w.y);
                    fma2(acc[6][0], pkdup(hb2.z), w.x); fma2(acc[6][1], pkdup(hb2.z), w.y);
                    fma2(acc[7][0], pkdup(hb2.w), w.x); fma2(acc[7][1], pkdup(hb2.w), w.y);
                }
                __syncwarp();
                if (lane == 0) MB_ARRIVE(mbe0 + (ci & 1) * 8);
                ci++;
            }
            // epilogue: activate + store quad
#pragma unroll
            for (int r = 0; r < 8; r++) {
                float a0, a1, a2, a3;
                upk(acc[r][0], a0, a1);
                upk(acc[r][1], a2, a3);
                float4 v;
                v.x = actp(a0, am1, as1, ab1); v.y = actp(a1, am1, as1, ab1);
                v.z = actp(a2, am1, as1, ab1); v.w = actp(a3, am1, as1, ab1);
                *(float4 *)&Gsm[(8 * rg + r) * NCOL + c0] = v;
            }
        }
        // phase-2 GEMM(t-1): g2 = act(b2 + [h1(t-1); h2(t-2)] @ W2), 128 thr
        if (tid < 128) {
            ull acc2[8][2];
            {
                ulonglong2 bq = *(const ulonglong2 *)&g_b2[c2c];
#pragma unroll
                for (int r = 0; r < 8; r++) { acc2[r][0] = bq.x; acc2[r][1] = bq.y; }
            }
            for (int wc = 0; wc < 4; wc++) {
                if (tid == 0) produce(ci + 1, ringb, mbf0, mbe0);
                MB_WAIT(mbf0 + (ci & 1) * 8, (ci >> 1) & 1);
                const float *wb = ring + (ci & 1) * 10240;
#pragma unroll
                for (int h2 = 0; h2 < 32; h2++) {
                    int h = wc * 32 + h2;
                    ulonglong2 w = *(const ulonglong2 *)&wb[h2 * 256 + c2c];
                    const float *hp = &hhT[h * HTS + 8 * rg2];
                    float4 ha = *(const float4 *)hp;
                    float4 hb2 = *(const float4 *)(hp + 4);
                    fma2(acc2[0][0], pkdup(ha.x), w.x);  fma2(acc2[0][1], pkdup(ha.x), w.y);
                    fma2(acc2[1][0], pkdup(ha.y), w.x);  fma2(acc2[1][1], pkdup(ha.y), w.y);
                    fma2(acc2[2][0], pkdup(ha.z), w.x);  fma2(acc2[2][1], pkdup(ha.z), w.y);
                    fma2(acc2[3][0], pkdup(ha.w), w.x);  fma2(acc2[3][1], pkdup(ha.w), w.y);
                    fma2(acc2[4][0], pkdup(hb2.x), w.x); fma2(acc2[4][1], pkdup(hb2.x), w.y);
                    fma2(acc2[5][0], pkdup(hb2.y), w.x); fma2(acc2[5][1], pkdup(hb2.y), w.y);
                    fma2(acc2[6][0], pkdup(hb2.z), w.x); fma2(acc2[6][1], pkdup(hb2.z), w.y);
                    fma2(acc2[7][0], pkdup(hb2.w), w.x); fma2(acc2[7][1], pkdup(hb2.w), w.y);
                }
                __syncwarp();
                if (lane == 0) MB_ARRIVE(mbe0 + (ci & 1) * 8);
                ci++;
            }
#pragma unroll
            for (int r = 0; r < 8; r++) {
                float a0, a1, a2, a3;
                upk(acc2[r][0], a0, a1);
                upk(acc2[r][1], a2, a3);
                float4 v;
                v.x = actp(a0, am2, as2, ab2); v.y = actp(a1, am2, as2, ab2);
                v.z = actp(a2, am2, as2, ab2); v.w = actp(a3, am2, as2, ab2);
                *(float4 *)&g2[(8 * rg2 + r) * 256 + c2c] = v;
            }
        } else {
            // warps 4..19: pass through the 4 ring chunks (keep arrive counts)
            for (int wc = 0; wc < 4; wc++) {
                MB_WAIT(mbf0 + (ci & 1) * 8, (ci >> 1) & 1);
                __syncwarp();
                if (lane == 0) MB_ARRIVE(mbe0 + (ci & 1) * 8);
                ci++;
            }
            // warps 4..11: attention matvec v = W_att @ c(t-1) for all rows
            if (tid < 384) {
                ull va0 = 0ull, va1 = 0ull;
                const float *cp = &csm[vr * HDIM];
#pragma unroll 8
                for (int g = 0; g < HDIM; g++) {
                    ull cd = pkdup(cp[g]);
                    ulonglong2 w = *(const ulonglong2 *)&g_WattT[g * HDIM + vc];
                    fma2(va0, cd, w.x);
                    fma2(va1, cd, w.y);
                }
                float a0, a1, a2, a3;
                upk(va0, a0, a1);
                upk(va1, a2, a3);
                *(float4 *)&vsm[vr * HDIM + vc] = make_float4(a0, a1, a2, a3);
            }
        }
        __syncthreads();

        // ================= PHASE B: ew2(t-1) then ew1(t) =====================
        if (warp < BT) {
            const int r = warp;
            // ---- ew2 for step t-1 (skip at t=0): reads g2, writes h2, out ----
            if (t > 0) {
                const float *gr = &g2[r * 256];
                const int w0i = lane, w1i = lane + 32;
                float ia0 = gr[w0i],        ia1 = gr[w1i];
                float fa0 = gr[64 + w0i],   fa1 = gr[64 + w1i];
                float ga0 = gr[128 + w0i],  ga1 = gr[128 + w1i];
                float oa0 = gr[192 + w0i],  oa1 = gr[192 + w1i];
                c2a = fmaf(fa0, c2a, ia0 * ga0);
                c2b = fmaf(fa1, c2b, ia1 * ga1);
                float h20 = oa0 * ftanh(c2a), h21 = oa1 * ftanh(c2b);
                hhT[(64 + w0i) * HTS + r] = h20;
                hhT[(64 + w1i) * HTS + r] = h21;
                float ov = fmaxf(h20, 0.f) * g_linW[w0i] + fmaxf(h21, 0.f) * g_linW[w1i];
                ov += __shfl_xor_sync(0xffffffffu, ov, 16);
                ov += __shfl_xor_sync(0xffffffffu, ov, 8);
                ov += __shfl_xor_sync(0xffffffffu, ov, 4);
                ov += __shfl_xor_sync(0xffffffffu, ov, 2);
                ov += __shfl_xor_sync(0xffffffffu, ov, 1);
                if (lane == 0) out[(size_t)(t - 1) * BSZ + b0 + r] = ov + linb;
            }
            // ---- ew1(t): attention + state update (matvec precomputed) ----
            {
                const float *Gr = &Gsm[r * NCOL];
                const int h0 = lane, h1 = lane + 32;

                float fa0 = Gr[64 + h0], fa1 = Gr[64 + h1];
                float oa0 = Gr[128 + h0], oa1 = Gr[128 + h1];

                float l0[9], l1[9];
                l0[0] = Gr[h0] * Gr[192 + h0];
                l1[0] = Gr[h1] * Gr[192 + h1];
#pragma unroll
                for (int k = 0; k < KAUX; k++) {
                    const float *Ga = Gr + 256 + 128 * k;
                    l0[k + 1] = Ga[h0] * Ga[64 + h0];
                    l1[k + 1] = Ga[h1] * Ga[64 + h1];
                }

                float v0 = vsm[r * HDIM + h0];
                float v1 = vsm[r * HDIM + h1];

                // u_k = tanh(l_k . v + b_att); softmax (u in (-1,1))
                float e[9], esum = 0.f;
#pragma unroll
                for (int k = 0; k < 9; k++) {
                    float d = l0[k] * v0 + l1[k] * v1;
                    d += __shfl_xor_sync(0xffffffffu, d, 16);
                    d += __shfl_xor_sync(0xffffffffu, d, 8);
                    d += __shfl_xor_sync(0xffffffffu, d, 4);
                    d += __shfl_xor_sync(0xffffffffu, d, 2);
                    d += __shfl_xor_sync(0xffffffffu, d, 1);
                    e[k] = __expf(ftanh(d + batt));
                    esum += e[k];
                }
                float inv = __fdividef(1.f, esum);
                float L0 = 0.f, L1 = 0.f;
#pragma unroll
                for (int k = 0; k < 9; k++) {
                    float a = e[k] * inv;
                    L0 = fmaf(a, l0[k], L0);
                    L1 = fmaf(a, l1[k], L1);
                }
                float cn0 = fmaf(fa0, c1a, L0), cn1 = fmaf(fa1, c1b, L1);
                float hn0 = oa0 * ftanh(cn0),   hn1 = oa1 * ftanh(cn1);
                c1a = cn0; c1b = cn1;
                csm[r * HDIM + h0] = cn0; csm[r * HDIM + h1] = cn1;
                hhT[h0 * HTS + r] = hn0;  hhT[h1 * HTS + r] = hn1;
            }
        }
        // stage x(t+1) into the alternate buffer (all threads)
        xnxt[d0] = pv0;
        if (j1 < NX) xnxt[d1] = pv1;
        __syncthreads();
    }

    // ================= epilogue: phase-2 + ew2 for step SEQ-1 ===============
    if (tid < 128) {
        ull acc2[8][2];
        {
            ulonglong2 bq = *(const ulonglong2 *)&g_b2[c2c];
#pragma unroll
            for (int r = 0; r < 8; r++) { acc2[r][0] = bq.x; acc2[r][1] = bq.y; }
        }
#pragma unroll 8
        for (int h = 0; h < 128; h++) {
            ulonglong2 w = *(const ulonglong2 *)&g_W2[h * 256 + c2c];
            const float *hp = &hhT[h * HTS + 8 * rg2];
            float4 ha = *(const float4 *)hp;
            float4 hb2 = *(const float4 *)(hp + 4);
            fma2(acc2[0][0], pkdup(ha.x), w.x);  fma2(acc2[0][1], pkdup(ha.x), w.y);
            fma2(acc2[1][0], pkdup(ha.y), w.x);  fma2(acc2[1][1], pkdup(ha.y), w.y);
            fma2(acc2[2][0], pkdup(ha.z), w.x);  fma2(acc2[2][1], pkdup(ha.z), w.y);
            fma2(acc2[3][0], pkdup(ha.w), w.x);  fma2(acc2[3][1], pkdup(ha.w), w.y);
            fma2(acc2[4][0], pkdup(hb2.x), w.x); fma2(acc2[4][1], pkdup(hb2.x), w.y);
            fma2(acc2[5][0], pkdup(hb2.y), w.x); fma2(acc2[5][1], pkdup(hb2.y), w.y);
            fma2(acc2[6][0], pkdup(hb2.z), w.x); fma2(acc2[6][1], pkdup(hb2.z), w.y);
            fma2(acc2[7][0], pkdup(hb2.w), w.x); fma2(acc2[7][1], pkdup(hb2.w), w.y);
        }
#pragma unroll
        for (int r = 0; r < 8; r++) {
            float a0, a1, a2, a3;
            upk(acc2[r][0], a0, a1);
            upk(acc2[r][1], a2, a3);
            float4 v;
            v.x = actp(a0, am2, as2, ab2); v.y = actp(a1, am2, as2, ab2);
            v.z = actp(a2, am2, as2, ab2); v.w = actp(a3, am2, as2, ab2);
            *(float4 *)&g2[(8 * rg2 + r) * 256 + c2c] = v;
        }
    }
    __syncthreads();
    if (warp < BT) {
        const int r = warp;
        const float *gr = &g2[r * 256];
        const int w0i = lane, w1i = lane + 32;
        float ia0 = gr[w0i],        ia1 = gr[w1i];
        float fa0 = gr[64 + w0i],   fa1 = gr[64 + w1i];
        float ga0 = gr[128 + w0i],  ga1 = gr[128 + w1i];
        float oa0 = gr[192 + w0i],  oa1 = gr[192 + w1i];
        c2a = fmaf(fa0, c2a, ia0 * ga0);
        c2b = fmaf(fa1, c2b, ia1 * ga1);
        float h20 = oa0 * ftanh(c2a), h21 = oa1 * ftanh(c2b);
        float ov = fmaxf(h20, 0.f) * g_linW[w0i] + fmaxf(h21, 0.f) * g_linW[w1i];
        ov += __shfl_xor_sync(0xffffffffu, ov, 16);
        ov += __shfl_xor_sync(0xffffffffu, ov, 8);
        ov += __shfl_xor_sync(0xffffffffu, ov, 4);
        ov += __shfl_xor_sync(0xffffffffu, ov, 2);
        ov += __shfl_xor_sync(0xffffffffu, ov, 1);
        if (lane == 0) out[(size_t)(SEQ - 1) * BSZ + b0 + r] = ov + linb;
    }
}

// ---------------- launch ----------------------------------------------------
extern "C" void kernel_launch(void *const *d_in, const int *in_sizes, int n_in,
                              void *d_out, int out_size) {
    (void)in_sizes; (void)n_in; (void)out_size;
    const float *Y    = (const float *)d_in[0];
    const float *x1   = (const float *)d_in[1];
    const float *x2   = (const float *)d_in[2];
    const float *x3   = (const float *)d_in[3];
    const float *x4   = (const float *)d_in[4];
    const float *x5   = (const float *)d_in[5];
    const float *x6   = (const float *)d_in[6];
    const float *x7   = (const float *)d_in[7];
    const float *x8   = (const float *)d_in[8];
    const float *Wm   = (const float *)d_in[9];
    const float *Um   = (const float *)d_in[10];
    const float *bm   = (const float *)d_in[11];
    const float *Wa   = (const float *)d_in[12];
    const float *Ua   = (const float *)d_in[13];
    const float *ba   = (const float *)d_in[14];
    const float *Watt = (const float *)d_in[15];
    const float *batt = (const float *)d_in[16];
    const float *Wih  = (const float *)d_in[17];
    const float *Whh  = (const float *)d_in[18];
    const float *bih  = (const float *)d_in[19];
    const float *bhh  = (const float *)d_in[20];
    const float *linW = (const float *)d_in[21];
    const float *linb = (const float *)d_in[22];
    float *out = (float *)d_out;

    prep_kernel<<<(HDIM * NCOL + 255) / 256, 256>>>(Wm, Um, bm, Wa, Ua, ba, Watt,
                                                    Wih, Whh, bih, bhh, linW);

    static_assert(SM_TOT * 4 < 227 * 1024, "smem");
    cudaFuncSetAttribute(mi_kernel, cudaFuncAttributeMaxDynamicSharedMemorySize,
                         SM_TOT * (int)sizeof(float));
    mi_kernel<<<NBLK, NTHR, SM_TOT * sizeof(float)>>>(Y, x1, x2, x3, x4, x5, x6, x7, x8,
                                                      batt, linb, out);
}

// round 14
// speedup vs baseline: 1.0748x; 1.0748x over previous
#include <cuda_runtime.h>
#include <cstdint>

typedef unsigned long long ull;

#define SEQ   256
#define BSZ   2048
#define FDIM  5
#define HDIM  64
#define KAUX  8
#define NCOL  1280           // 256 (main gates) + 8*128 (aux gates)
#define BT    16             // batch rows per block
#define NTHR  640            // 20 warps: 2 row-groups x 320 col-quads
#define NBLK  (BSZ / BT)     // 128 blocks, 1 per SM
#define NX    720            // 9*16*5 staged x values per step
#define HTS   20             // hhT row stride in floats (80B, 16B-aligned)

#define CHPS  12             // chunks per step: 8 Ucat + 4 W2
#define TOTC  (CHPS * SEQ)   // total chunks over the sequence

// ---------------- repacked weights (device globals; prep kernel fills) ------
__device__ __align__(16) float g_Ucat[HDIM * NCOL];   // [h][col]  recurrent cat
__device__ __align__(16) float g_Wx[FDIM * NCOL];     // [f][col]  input proj cat
__device__ __align__(16) float g_bcat[NCOL];          // bias cat
__device__ __align__(16) float g_W2[128 * 256];       // [h<64:Wih^T, h>=64:Whh^T][j]
__device__ __align__(16) float g_b2[256];             // b_ih + b_hh
__device__ __align__(16) float g_WattT[HDIM * HDIM];  // [g][h] = W_att[h][g]
__device__ __align__(16) float g_linW[HDIM];

// ---------------- f32x2 helpers ---------------------------------------------
__device__ __forceinline__ void fma2(ull &d, ull a, ull b) {
    asm("fma.rn.f32x2 %0, %1, %2, %0;" : "+l"(d) : "l"(a), "l"(b));
}
__device__ __forceinline__ ull pkdup(float v) {
    ull r; asm("mov.b64 %0, {%1,%1};" : "=l"(r) : "f"(v)); return r;
}
__device__ __forceinline__ void upk(ull v, float &lo, float &hi) {
    asm("mov.b64 {%0,%1}, %2;" : "=f"(lo), "=f"(hi) : "l"(v));
}

// ---------------- fast activations ------------------------------------------
__device__ __forceinline__ float fsig(float x) {
    float e = __expf(-x);
    return __fdividef(1.f, 1.f + e);
}
__device__ __forceinline__ float ftanh(float x) {
    return 2.f * fsig(2.f * x) - 1.f;
}
// branch-free sig/tanh: out = fsig(x*am)*asc + ab  (sig: 1,1,0 ; tanh: 2,2,-1)
__device__ __forceinline__ float actp(float x, float am, float asc, float ab) {
    return fmaf(fsig(x * am), asc, ab);
}

// ---------------- mbarrier / bulk-copy PTX ----------------------------------
#define MB_INIT(addr, cnt) \
    asm volatile("mbarrier.init.shared.b64 [%0], %1;" :: "r"(addr), "r"(cnt) : "memory")
#define MB_EXPECT_TX(addr, bytes) \
    asm volatile("mbarrier.arrive.expect_tx.shared.b64 _, [%0], %1;" :: "r"(addr), "r"(bytes) : "memory")
#define MB_ARRIVE(addr) \
    asm volatile("mbarrier.arrive.shared.b64 _, [%0];" :: "r"(addr) : "memory")
#define MB_WAIT(addr, par) do {                                                 \
    uint32_t _m = (addr), _p = (par), _d;                                       \
    asm volatile("{\n\t.reg .pred p;\n\t"                                       \
        "mbarrier.try_wait.parity.acquire.cta.shared::cta.b64 p, [%1], %2;\n\t" \
        "selp.b32 %0, 1, 0, p;\n\t}"                                            \
        : "=r"(_d) : "r"(_m), "r"(_p) : "memory");                              \
    if (!_d) {                                                                  \
        asm volatile("{\n\t.reg .pred P1;\n\t"                                  \
            "W_%=:\n\t"                                                         \
            "mbarrier.try_wait.parity.acquire.cta.shared::cta.b64 P1, [%0], %1, 0x989680;\n\t" \
            "@P1 bra.uni D_%=;\n\t"                                             \
            "bra.uni W_%=;\n\t"                                                 \
            "D_%=:\n\t}" :: "r"(_m), "r"(_p) : "memory");                       \
    }                                                                           \
} while (0)
#define BULK_G2S(dst, src, bytes, mbar) \
    asm volatile("cp.async.bulk.shared::cluster.global.mbarrier::complete_tx::bytes " \
                 "[%0], [%1], %2, [%3];" \
                 :: "r"(dst), "l"((const void *)(src)), "r"(bytes), "r"(mbar) : "memory")

// producer: issue DMA for chunk cj (tid 0 only)
__device__ __forceinline__ void produce(int cj, uint32_t ringb, uint32_t mbf0, uint32_t mbe0) {
    if (cj >= TOTC) return;
    if (cj >= 2) MB_WAIT(mbe0 + (cj & 1) * 8, ((cj >> 1) + 1) & 1);
    int m = cj % CHPS;
    const float *src;
    uint32_t bytes;
    if (m < 8) { src = g_Ucat + m * (8 * NCOL);       bytes = 8 * NCOL * 4; }   // 40960
    else       { src = g_W2   + (m - 8) * (32 * 256); bytes = 32 * 256 * 4; }   // 32768
    uint32_t fb = mbf0 + (cj & 1) * 8;
    MB_EXPECT_TX(fb, bytes);
    BULK_G2S(ringb + (cj & 1) * 40960u, src, bytes, fb);
}

// ---------------- prep: repack weights --------------------------------------
__global__ void prep_kernel(const float *__restrict__ Wm, const float *__restrict__ Um,
                            const float *__restrict__ bm, const float *__restrict__ Wa,
                            const float *__restrict__ Ua, const float *__restrict__ ba,
                            const float *__restrict__ Watt, const float *__restrict__ Wih,
                            const float *__restrict__ Whh, const float *__restrict__ bih,
                            const float *__restrict__ bhh, const float *__restrict__ linW) {
    int i = blockIdx.x * blockDim.x + threadIdx.x;
    if (i < HDIM * NCOL) {
        int h = i / NCOL, col = i % NCOL;
        float v;
        if (col < 256) v = Um[h * 256 + col];
        else { int cc = col - 256; int k = cc >> 7, j = cc & 127; v = Ua[(k * HDIM + h) * 128 + j]; }
        g_Ucat[i] = v;
    }
    if (i < FDIM * NCOL) {
        int f = i / NCOL, col = i % NCOL;
        float v;
        if (col < 256) v = Wm[f * 256 + col];
        else { int cc = col - 256; int k = cc >> 7, j = cc & 127; v = Wa[(k * FDIM + f) * 128 + j]; }
        g_Wx[i] = v;
    }
    if (i < NCOL) g_bcat[i] = (i < 256) ? bm[i] : ba[i - 256];
    if (i < 128 * 256) {
        int h = i / 256, j = i % 256;
        g_W2[i] = (h < 64) ? Wih[j * 64 + h] : Whh[j * 64 + (h - 64)];
    }
    if (i < 256) g_b2[i] = bih[i] + bhh[i];
    if (i < HDIM * HDIM) { int g = i / HDIM, h = i % HDIM; g_WattT[i] = Watt[h * HDIM + g]; }
    if (i < HDIM) g_linW[i] = linW[i];
}

// ---------------- smem layout (float offsets) -------------------------------
#define SM_G    0                       // G[16][1280] activated    20480
#define SM_G2   20480                   // g2[16][256] activated     4096
#define SM_HT   24576                   // hhT[128][20]              2560
#define SM_C    27136                   // c1[16][64]                1024
#define SM_X    28160                   // x double buffer 2x720     1440
#define SM_RING 29600                   // 2 x 10240 weight ring    20480
#define SM_MB   50080                   // 4 mbarriers (8 floats)       8
#define SM_PT   50088                   // 9 input base ptrs (18 fl)   20
#define SM_V    50108                   // vsm[16][64] attn matvec   1024
#define SM_TOT  51132                   // 204528 bytes

__global__ void __launch_bounds__(NTHR, 1)
mi_kernel(const float *__restrict__ Y,
          const float *__restrict__ X1, const float *__restrict__ X2,
          const float *__restrict__ X3, const float *__restrict__ X4,
          const float *__restrict__ X5, const float *__restrict__ X6,
          const float *__restrict__ X7, const float *__restrict__ X8,
          const float *__restrict__ batt_p, const float *__restrict__ linb_p,
          float *__restrict__ out) {
    extern __shared__ float sm[];
    float *Gsm  = sm + SM_G;
    float *g2   = sm + SM_G2;
    float *hhT  = sm + SM_HT;     // [h(0..63:h1, 64..127:h2)][row], stride HTS
    float *csm  = sm + SM_C;
    float *xsm  = sm + SM_X;      // two 720-float buffers
    float *ring = sm + SM_RING;
    float *vsm  = sm + SM_V;      // v[r][h] = (W_att @ c(t-1))[h]
    const float **ptab = (const float **)(sm + SM_PT);

    uint32_t sbase;
    asm("{ .reg .u64 t; cvta.to.shared.u64 t, %1; cvt.u32.u64 %0, t; }"
        : "=r"(sbase) : "l"(sm));
    const uint32_t ringb = sbase + SM_RING * 4;
    const uint32_t mbf0  = sbase + SM_MB * 4;        // full[0], full[1]
    const uint32_t mbe0  = mbf0 + 16;                // empty[0], empty[1]

    const int tid  = threadIdx.x;
    const int warp = tid >> 5, lane = tid & 31;
    const int rg = (tid >= 320) ? 1 : 0;   // row-group: rows 8rg..8rg+7
    const int q  = tid - rg * 320;         // col-quad 0..319 (cols 4q..4q+3)
    const int c0 = 4 * q;
    const int b0 = blockIdx.x * BT;

    const float batt = *batt_p;
    const float linb = *linb_p;

    // phase-1 quad metadata
    const bool p1_sig = (c0 < 256) ? ((c0 >> 6) < 3) : (((c0 - 256) & 127) < 64);
    const int  xsrc   = (c0 < 256) ? 0 : 1 + ((c0 - 256) >> 7);
    const float am1 = p1_sig ? 1.f : 2.f, as1 = p1_sig ? 1.f : 2.f, ab1 = p1_sig ? 0.f : -1.f;

    // phase-2 mapping (threads 0..255): 4 row-groups x 64 col-quads
    const int rg2 = tid >> 6;              // rows 4*rg2..4*rg2+3
    const int q2  = tid & 63;              // cols 4*q2..4*q2+3
    const int c2c = 4 * q2;
    const bool p2_sig = ((c2c >> 6) != 2);
    const float am2 = p2_sig ? 1.f : 2.f, as2 = p2_sig ? 1.f : 2.f, ab2 = p2_sig ? 0.f : -1.f;

    // attention matvec mapping (threads 256..511): 16 rows x 16 col-quads
    const int mv  = tid - 256;             // 0..255
    const int vr  = mv >> 4;               // row 0..15
    const int vc  = 4 * (mv & 15);         // col 0,4,..,60

    // init: ptr table, mbarriers, zero state
    {
        const float *xin[9] = {Y, X1, X2, X3, X4, X5, X6, X7, X8};
        if (tid < 9) ptab[tid] = xin[tid];
    }
    if (tid == 0) {
        MB_INIT(mbf0, 1);  MB_INIT(mbf0 + 8, 1);
        MB_INIT(mbe0, 20); MB_INIT(mbe0 + 8, 20);   // one arrive per warp
    }
    for (int i = tid; i < 128 * HTS; i += NTHR) hhT[i] = 0.f;
    for (int i = tid; i < 1024; i += NTHR) csm[i] = 0.f;
    float c1a = 0.f, c1b = 0.f;   // phase-1 cell, h = lane / lane+32 of row `warp`
    float c2a = 0.f, c2b = 0.f;   // phase-2 cell
    __syncthreads();

    // stage inputs for t=0 into buffer 0; set up per-thread prefetch pointers
    for (int j = tid; j < NX; j += NTHR) {
        int s = j / 80, rem = j - s * 80;
        int row = rem / 5, f = rem - row * 5;
        xsm[s * 80 + f * 16 + row] = ptab[s][(size_t)b0 * FDIM + rem];
    }
    const int j0 = tid, j1 = tid + NTHR;           // j1 < 720 only for tid<80
    const int s0 = j0 / 80, rem0 = j0 - s0 * 80;
    const int d0 = s0 * 80 + (rem0 % 5) * 16 + rem0 / 5;
    const int s1 = (j1 < NX) ? j1 / 80 : 0;
    const int rem1 = j1 - s1 * 80;
    const int d1 = (j1 < NX) ? s1 * 80 + (rem1 % 5) * 16 + rem1 / 5 : 0;
    const float *pp0 = ptab[s0] + (size_t)b0 * FDIM + rem0;
    const float *pp1 = ptab[s1] + (size_t)b0 * FDIM + rem1;

    __syncthreads();
    if (tid == 0) produce(0, ringb, mbf0, mbe0);    // kick off the ring
    int ci = 0;                                     // global chunk cursor

    for (int t = 0; t < SEQ; t++) {
        const float *xcur = xsm + (t & 1) * NX;
        float *xnxt = xsm + ((t + 1) & 1) * NX;

        // ---- issue x(t+1) loads now; stored at end of step (latency hidden)
        float pv0, pv1 = 0.f;
        {
            size_t toff = (size_t)((t + 1 < SEQ) ? t + 1 : t) * (BSZ * FDIM);
            pv0 = __ldg(pp0 + toff);
            if (j1 < NX) pv1 = __ldg(pp1 + toff);
        }

        // ================= PHASE A: both GEMMs + attn matvec =================
        // phase-1 GEMM(t): G = act(b + x(t)@Wx + h1(t-1)@Ucat)
        {
            ull acc[8][2];
            {
                ulonglong2 bq = *(const ulonglong2 *)&g_bcat[c0];
#pragma unroll
                for (int r = 0; r < 8; r++) { acc[r][0] = bq.x; acc[r][1] = bq.y; }
            }
            // x contribution (K=5)
#pragma unroll
            for (int f = 0; f < FDIM; f++) {
                ulonglong2 w = *(const ulonglong2 *)&g_Wx[f * NCOL + c0];
                const float *xb = &xcur[xsrc * 80 + f * 16 + 8 * rg];
                float4 xa = *(const float4 *)xb;
                float4 xc = *(const float4 *)(xb + 4);
                fma2(acc[0][0], pkdup(xa.x), w.x); fma2(acc[0][1], pkdup(xa.x), w.y);
                fma2(acc[1][0], pkdup(xa.y), w.x); fma2(acc[1][1], pkdup(xa.y), w.y);
                fma2(acc[2][0], pkdup(xa.z), w.x); fma2(acc[2][1], pkdup(xa.z), w.y);
                fma2(acc[3][0], pkdup(xa.w), w.x); fma2(acc[3][1], pkdup(xa.w), w.y);
                fma2(acc[4][0], pkdup(xc.x), w.x); fma2(acc[4][1], pkdup(xc.x), w.y);
                fma2(acc[5][0], pkdup(xc.y), w.x); fma2(acc[5][1], pkdup(xc.y), w.y);
                fma2(acc[6][0], pkdup(xc.z), w.x); fma2(acc[6][1], pkdup(xc.z), w.y);
                fma2(acc[7][0], pkdup(xc.w), w.x); fma2(acc[7][1], pkdup(xc.w), w.y);
            }
            // h contribution: 8 ring chunks x 8 h-rows
            for (int hc = 0; hc < 8; hc++) {
                if (tid == 0) produce(ci + 1, ringb, mbf0, mbe0);
                MB_WAIT(mbf0 + (ci & 1) * 8, (ci >> 1) & 1);
                const float *wb = ring + (ci & 1) * 10240;
#pragma unroll
                for (int h2 = 0; h2 < 8; h2++) {
                    int h = hc * 8 + h2;
                    ulonglong2 w = *(const ulonglong2 *)&wb[h2 * NCOL + c0];
                    const float *hp = &hhT[h * HTS + 8 * rg];
                    float4 ha = *(const float4 *)hp;
                    float4 hb2 = *(const float4 *)(hp + 4);
                    fma2(acc[0][0], pkdup(ha.x), w.x);  fma2(acc[0][1], pkdup(ha.x), w.y);
                    fma2(acc[1][0], pkdup(ha.y), w.x);  fma2(acc[1][1], pkdup(ha.y), w.y);
                    fma2(acc[2][0], pkdup(ha.z), w.x);  fma2(acc[2][1], pkdup(ha.z), w.y);
                    fma2(acc[3][0], pkdup(ha.w), w.x);  fma2(acc[3][1], pkdup(ha.w), w.y);
                    fma2(acc[4][0], pkdup(hb2.x), w.x); fma2(acc[4][1], pkdup(hb2.x), w.y);
                    fma2(acc[5][0], pkdup(hb2.y), w.x); fma2(acc[5][1], pkdup(hb2.y), w.y);
                    fma2(acc[6][0], pkdup(hb2.z), w.x); fma2(acc[6][1], pkdup(hb2.z), w.y);
                    fma2(acc[7][0], pkdup(hb2.w), w.x); fma2(acc[7][1], pkdup(hb2.w), w.y);
                }
                __syncwarp();
                if (lane == 0) MB_ARRIVE(mbe0 + (ci & 1) * 8);
                ci++;
            }
            // epilogue: activate + store quad
#pragma unroll
            for (int r = 0; r < 8; r++) {
                float a0, a1, a2, a3;
                upk(acc[r][0], a0, a1);
                upk(acc[r][1], a2, a3);
                float4 v;
                v.x = actp(a0, am1, as1, ab1); v.y = actp(a1, am1, as1, ab1);
                v.z = actp(a2, am1, as1, ab1); v.w = actp(a3, am1, as1, ab1);
                *(float4 *)&Gsm[(8 * rg + r) * NCOL + c0] = v;
            }
        }
        // phase-2 GEMM(t-1): g2 = act(b2 + [h1(t-1); h2(t-2)] @ W2), 256 thr
        if (tid < 256) {
            ull acc2[4][2];
            {
                ulonglong2 bq = *(const ulonglong2 *)&g_b2[c2c];
#pragma unroll
                for (int r = 0; r < 4; r++) { acc2[r][0] = bq.x; acc2[r][1] = bq.y; }
            }
            for (int wc = 0; wc < 4; wc++) {
                if (tid == 0) produce(ci + 1, ringb, mbf0, mbe0);
                MB_WAIT(mbf0 + (ci & 1) * 8, (ci >> 1) & 1);
                const float *wb = ring + (ci & 1) * 10240;
#pragma unroll
                for (int h2 = 0; h2 < 32; h2++) {
                    int h = wc * 32 + h2;
                    ulonglong2 w = *(const ulonglong2 *)&wb[h2 * 256 + c2c];
                    float4 hv = *(const float4 *)&hhT[h * HTS + 4 * rg2];
                    fma2(acc2[0][0], pkdup(hv.x), w.x); fma2(acc2[0][1], pkdup(hv.x), w.y);
                    fma2(acc2[1][0], pkdup(hv.y), w.x); fma2(acc2[1][1], pkdup(hv.y), w.y);
                    fma2(acc2[2][0], pkdup(hv.z), w.x); fma2(acc2[2][1], pkdup(hv.z), w.y);
                    fma2(acc2[3][0], pkdup(hv.w), w.x); fma2(acc2[3][1], pkdup(hv.w), w.y);
                }
                __syncwarp();
                if (lane == 0) MB_ARRIVE(mbe0 + (ci & 1) * 8);
                ci++;
            }
#pragma unroll
            for (int r = 0; r < 4; r++) {
                float a0, a1, a2, a3;
                upk(acc2[r][0], a0, a1);
                upk(acc2[r][1], a2, a3);
                float4 v;
                v.x = actp(a0, am2, as2, ab2); v.y = actp(a1, am2, as2, ab2);
                v.z = actp(a2, am2, as2, ab2); v.w = actp(a3, am2, as2, ab2);
                *(float4 *)&g2[(4 * rg2 + r) * 256 + c2c] = v;
            }
        } else {
            // warps 8..19: pass through the 4 ring chunks (keep arrive counts)
            for (int wc = 0; wc < 4; wc++) {
                MB_WAIT(mbf0 + (ci & 1) * 8, (ci >> 1) & 1);
                __syncwarp();
                if (lane == 0) MB_ARRIVE(mbe0 + (ci & 1) * 8);
                ci++;
            }
            // warps 8..15: attention matvec v = W_att @ c(t-1) for all rows
            if (tid < 512) {
                ull va0 = 0ull, va1 = 0ull;
                const float *cp = &csm[vr * HDIM];
#pragma unroll 8
                for (int g = 0; g < HDIM; g++) {
                    ull cd = pkdup(cp[g]);
                    ulonglong2 w = *(const ulonglong2 *)&g_WattT[g * HDIM + vc];
                    fma2(va0, cd, w.x);
                    fma2(va1, cd, w.y);
                }
                float a0, a1, a2, a3;
                upk(va0, a0, a1);
                upk(va1, a2, a3);
                *(float4 *)&vsm[vr * HDIM + vc] = make_float4(a0, a1, a2, a3);
            }
        }
        __syncthreads();

        // ================= PHASE B: ew2(t-1) then ew1(t) =====================
        if (warp < BT) {
            const int r = warp;
            // ---- ew2 for step t-1 (skip at t=0): reads g2, writes h2, out ----
            if (t > 0) {
                const float *gr = &g2[r * 256];
                const int w0i = lane, w1i = lane + 32;
                float ia0 = gr[w0i],        ia1 = gr[w1i];
                float fa0 = gr[64 + w0i],   fa1 = gr[64 + w1i];
                float ga0 = gr[128 + w0i],  ga1 = gr[128 + w1i];
                float oa0 = gr[192 + w0i],  oa1 = gr[192 + w1i];
                c2a = fmaf(fa0, c2a, ia0 * ga0);
                c2b = fmaf(fa1, c2b, ia1 * ga1);
                float h20 = oa0 * ftanh(c2a), h21 = oa1 * ftanh(c2b);
                hhT[(64 + w0i) * HTS + r] = h20;
                hhT[(64 + w1i) * HTS + r] = h21;
                float ov = fmaxf(h20, 0.f) * g_linW[w0i] + fmaxf(h21, 0.f) * g_linW[w1i];
                ov += __shfl_xor_sync(0xffffffffu, ov, 16);
                ov += __shfl_xor_sync(0xffffffffu, ov, 8);
                ov += __shfl_xor_sync(0xffffffffu, ov, 4);
                ov += __shfl_xor_sync(0xffffffffu, ov, 2);
                ov += __shfl_xor_sync(0xffffffffu, ov, 1);
                if (lane == 0) out[(size_t)(t - 1) * BSZ + b0 + r] = ov + linb;
            }
            // ---- ew1(t): attention + state update (matvec precomputed) ----
            {
                const float *Gr = &Gsm[r * NCOL];
                const int h0 = lane, h1 = lane + 32;

                float fa0 = Gr[64 + h0], fa1 = Gr[64 + h1];
                float oa0 = Gr[128 + h0], oa1 = Gr[128 + h1];

                float l0[9], l1[9];
                l0[0] = Gr[h0] * Gr[192 + h0];
                l1[0] = Gr[h1] * Gr[192 + h1];
#pragma unroll
                for (int k = 0; k < KAUX; k++) {
                    const float *Ga = Gr + 256 + 128 * k;
                    l0[k + 1] = Ga[h0] * Ga[64 + h0];
                    l1[k + 1] = Ga[h1] * Ga[64 + h1];
                }

                float v0 = vsm[r * HDIM + h0];
                float v1 = vsm[r * HDIM + h1];

                // u_k = tanh(l_k . v + b_att); softmax (u in (-1,1))
                float e[9], esum = 0.f;
#pragma unroll
                for (int k = 0; k < 9; k++) {
                    float d = l0[k] * v0 + l1[k] * v1;
                    d += __shfl_xor_sync(0xffffffffu, d, 16);
                    d += __shfl_xor_sync(0xffffffffu, d, 8);
                    d += __shfl_xor_sync(0xffffffffu, d, 4);
                    d += __shfl_xor_sync(0xffffffffu, d, 2);
                    d += __shfl_xor_sync(0xffffffffu, d, 1);
                    e[k] = __expf(ftanh(d + batt));
                    esum += e[k];
                }
                float inv = __fdividef(1.f, esum);
                float L0 = 0.f, L1 = 0.f;
#pragma unroll
                for (int k = 0; k < 9; k++) {
                    float a = e[k] * inv;
                    L0 = fmaf(a, l0[k], L0);
                    L1 = fmaf(a, l1[k], L1);
                }
                float cn0 = fmaf(fa0, c1a, L0), cn1 = fmaf(fa1, c1b, L1);
                float hn0 = oa0 * ftanh(cn0),   hn1 = oa1 * ftanh(cn1);
                c1a = cn0; c1b = cn1;
                csm[r * HDIM + h0] = cn0; csm[r * HDIM + h1] = cn1;
                hhT[h0 * HTS + r] = hn0;  hhT[h1 * HTS + r] = hn1;
            }
        }
        // stage x(t+1) into the alternate buffer (all threads)
        xnxt[d0] = pv0;
        if (j1 < NX) xnxt[d1] = pv1;
        __syncthreads();
    }

    // ================= epilogue: phase-2 + ew2 for step SEQ-1 ===============
    if (tid < 256) {
        ull acc2[4][2];
        {
            ulonglong2 bq = *(const ulonglong2 *)&g_b2[c2c];
#pragma unroll
            for (int r = 0; r < 4; r++) { acc2[r][0] = bq.x; acc2[r][1] = bq.y; }
        }
#pragma unroll 8
        for (int h = 0; h < 128; h++) {
            ulonglong2 w = *(const ulonglong2 *)&g_W2[h * 256 + c2c];
            float4 hv = *(const float4 *)&hhT[h * HTS + 4 * rg2];
            fma2(acc2[0][0], pkdup(hv.x), w.x); fma2(acc2[0][1], pkdup(hv.x), w.y);
            fma2(acc2[1][0], pkdup(hv.y), w.x); fma2(acc2[1][1], pkdup(hv.y), w.y);
            fma2(acc2[2][0], pkdup(hv.z), w.x); fma2(acc2[2][1], pkdup(hv.z), w.y);
            fma2(acc2[3][0], pkdup(hv.w), w.x); fma2(acc2[3][1], pkdup(hv.w), w.y);
        }
#pragma unroll
        for (int r = 0; r < 4; r++) {
            float a0, a1, a2, a3;
            upk(acc2[r][0], a0, a1);
            upk(acc2[r][1], a2, a3);
            float4 v;
            v.x = actp(a0, am2, as2, ab2); v.y = actp(a1, am2, as2, ab2);
            v.z = actp(a2, am2, as2, ab2); v.w = actp(a3, am2, as2, ab2);
            *(float4 *)&g2[(4 * rg2 + r) * 256 + c2c] = v;
        }
    }
    __syncthreads();
    if (warp < BT) {
        const int r = warp;
        const float *gr = &g2[r * 256];
        const int w0i = lane, w1i = lane + 32;
        float ia0 = gr[w0i],        ia1 = gr[w1i];
        float fa0 = gr[64 + w0i],   fa1 = gr[64 + w1i];
        float ga0 = gr[128 + w0i],  ga1 = gr[128 + w1i];
        float oa0 = gr[192 + w0i],  oa1 = gr[192 + w1i];
        c2a = fmaf(fa0, c2a, ia0 * ga0);
        c2b = fmaf(fa1, c2b, ia1 * ga1);
        float h20 = oa0 * ftanh(c2a), h21 = oa1 * ftanh(c2b);
        float ov = fmaxf(h20, 0.f) * g_linW[w0i] + fmaxf(h21, 0.f) * g_linW[w1i];
        ov += __shfl_xor_sync(0xffffffffu, ov, 16);
        ov += __shfl_xor_sync(0xffffffffu, ov, 8);
        ov += __shfl_xor_sync(0xffffffffu, ov, 4);
        ov += __shfl_xor_sync(0xffffffffu, ov, 2);
        ov += __shfl_xor_sync(0xffffffffu, ov, 1);
        if (lane == 0) out[(size_t)(SEQ - 1) * BSZ + b0 + r] = ov + linb;
    }
}

// ---------------- launch ----------------------------------------------------
extern "C" void kernel_launch(void *const *d_in, const int *in_sizes, int n_in,
                              void *d_out, int out_size) {
    (void)in_sizes; (void)n_in; (void)out_size;
    const float *Y    = (const float *)d_in[0];
    const float *x1   = (const float *)d_in[1];
    const float *x2   = (const float *)d_in[2];
    const float *x3   = (const float *)d_in[3];
    const float *x4   = (const float *)d_in[4];
    const float *x5   = (const float *)d_in[5];
    const float *x6   = (const float *)d_in[6];
    const float *x7   = (const float *)d_in[7];
    const float *x8   = (const float *)d_in[8];
    const float *Wm   = (const float *)d_in[9];
    const float *Um   = (const float *)d_in[10];
    const float *bm   = (const float *)d_in[11];
    const float *Wa   = (const float *)d_in[12];
    const float *Ua   = (const float *)d_in[13];
    const float *ba   = (const float *)d_in[14];
    const float *Watt = (const float *)d_in[15];
    const float *batt = (const float *)d_in[16];
    const float *Wih  = (const float *)d_in[17];
    const float *Whh  = (const float *)d_in[18];
    const float *bih  = (const float *)d_in[19];
    const float *bhh  = (const float *)d_in[20];
    const float *linW = (const float *)d_in[21];
    const float *linb = (const float *)d_in[22];
    float *out = (float *)d_out;

    prep_kernel<<<(HDIM * NCOL + 255) / 256, 256>>>(Wm, Um, bm, Wa, Ua, ba, Watt,
                                                    Wih, Whh, bih, bhh, linW);

    static_assert(SM_TOT * 4 < 227 * 1024, "smem");
    cudaFuncSetAttribute(mi_kernel, cudaFuncAttributeMaxDynamicSharedMemorySize,
                         SM_TOT * (int)sizeof(float));
    mi_kernel<<<NBLK, NTHR, SM_TOT * sizeof(float)>>>(Y, x1, x2, x3, x4, x5, x6, x7, x8,
                                                      batt, linb, out);
}